// round 8
// baseline (speedup 1.0000x reference)
#include <cuda_runtime.h>
#include <math_constants.h>

#define NSEG 128
#define P    512
#define D    64
#define KT   15
#define NC   8
#define NT   1024
#define NW   (NT/32)
#define PAD  17

__device__ float g_partials[NSEG];
__device__ int   g_ticket = 0;   // reset by last block each launch

__global__ __launch_bounds__(NT, 1)
void lmnn_fused_kernel(const float* __restrict__ center,
                       const float* __restrict__ outputs,
                       const int*   __restrict__ labels,
                       float*       __restrict__ out)
{
    __shared__ float spart[P][PAD];   // per-point partial sums (pad: no conflicts)
    __shared__ float sdist[P];
    __shared__ int   slab[P];
    __shared__ short sidx[NC][16];
    __shared__ int   sCnt[NC];
    __shared__ int   sTaken[NC];
    __shared__ float sS[NC];
    __shared__ float sM[NC];
    __shared__ float sred[NW];
    __shared__ int   s_last;

    const int seg  = blockIdx.x;
    const int t    = threadIdx.x;
    const int w    = t >> 5;
    const int lane = t & 31;
    const int col  = t & 15;

    // ---- Issue the big loads FIRST (front-batched, coalesced, streaming) ----
    // 8192 float4s/segment; thread t takes g = t + 1024*s. (t&15) = d-offset.
    const float4* __restrict__ out4 = (const float4*)(outputs + (size_t)seg * P * D);
    float4 v[8];
    #pragma unroll
    for (int s = 0; s < 8; ++s)
        v[s] = __ldcs(&out4[t + NT * s]);
    const float4 c4 = __ldg(&((const float4*)(center + seg * D))[col]);

    // ---- class scan on labels (warps 0..7), hidden under load flight ----
    // top_k over -dd has all finite entries equal (dist broadcast along k),
    // so jax tie-breaking selects the FIRST KT same-class indices.
    if (w < NC) {
        int lab[16];
        #pragma unroll
        for (int u = 0; u < 16; ++u)
            lab[u] = __ldg(&labels[seg * P + u * 32 + lane]);
        if (w == 0) {
            #pragma unroll
            for (int u = 0; u < 16; ++u)
                slab[u * 32 + lane] = lab[u];
        }
        int cnt = 0, taken = 0;
        #pragma unroll
        for (int u = 0; u < 16; ++u) {
            const bool m = (lab[u] == w);
            const unsigned mask = __ballot_sync(0xffffffffu, m);
            const int pc = __popc(mask);
            const int need = KT - taken;
            if (need > 0) {
                const int rank = __popc(mask & ((1u << lane) - 1u));
                if (m && rank < need)
                    sidx[w][taken + rank] = (short)(u * 32 + lane);
                taken += (pc < need) ? pc : need;
            }
            cnt += pc;
        }
        if (lane == 0) { sCnt[w] = cnt; sTaken[w] = taken; }
    }

    // ---- distance partials: NO shuffles; write to padded smem ----
    #pragma unroll
    for (int s = 0; s < 8; ++s) {
        const int g = t + NT * s;          // float4 index in segment
        const float dx = v[s].x - c4.x;
        const float dy = v[s].y - c4.y;
        const float dz = v[s].z - c4.z;
        const float dw = v[s].w - c4.w;
        spart[g >> 4][col] = dx * dx + dy * dy + dz * dz + dw * dw;
    }
    __syncthreads();

    // ---- per-point serial sum (threads 0..511), conflict-free via PAD ----
    if (t < P) {
        const float* row = spart[t];
        float a0 = row[0] + row[1];
        float a1 = row[2] + row[3];
        float a2 = row[4] + row[5];
        float a3 = row[6] + row[7];
        float b0 = row[8] + row[9];
        float b1 = row[10] + row[11];
        float b2 = row[12] + row[13];
        float b3 = row[14] + row[15];
        sdist[t] = ((a0 + a1) + (a2 + a3)) + ((b0 + b1) + (b2 + b3));
    }
    __syncthreads();

    // ---- gather first-KT distances per class (warps 0..7) ----
    if (w < NC) {
        const int cnt   = sCnt[w];
        const int taken = sTaken[w];
        float d = (lane < KT)
                    ? ((lane < taken) ? sdist[sidx[w][lane]] : CUDART_INF_F)
                    : 0.0f;
        float S  = (lane < KT) ? d : 0.0f;
        float Mx = (lane < KT) ? d : -CUDART_INF_F;
        #pragma unroll
        for (int off = 16; off > 0; off >>= 1) {
            S += __shfl_xor_sync(0xffffffffu, S, off);
            Mx = fmaxf(Mx, __shfl_xor_sync(0xffffffffu, Mx, off));
        }
        if (lane == 0) {
            sS[w] = (cnt > 0) ? S : 0.0f;
            sM[w] = (cnt > 0) ? Mx : -CUDART_INF_F;
        }
    }
    __syncthreads();

    // ---- margin_seg = 1 + max over present classes ----
    float ms = -CUDART_INF_F;
    #pragma unroll
    for (int c = 0; c < NC; ++c)
        ms = fmaxf(ms, sM[c]);
    ms += 1.0f;

    // ---- push term per point (first 512 threads) ----
    float term = 0.0f;
    if (t < P) {
        const int   cj = slab[t];
        const float dv = sdist[t];
        if (dv < ms)
            term = (float)(P - sCnt[cj]) * fmaxf(1.0f + sM[cj] - dv, 0.0f);
    }
    #pragma unroll
    for (int off = 16; off > 0; off >>= 1)
        term += __shfl_xor_sync(0xffffffffu, term, off);
    if (lane == 0) sred[w] = term;
    __syncthreads();

    // ---- per-segment partial + last-block finish ----
    if (t == 0) {
        float push = 0.0f;
        #pragma unroll
        for (int k = 0; k < NW; ++k) push += sred[k];
        float pull = 0.0f;
        #pragma unroll
        for (int c = 0; c < NC; ++c)
            pull += (float)sCnt[c] * sS[c];
        g_partials[seg] = pull + push;
        __threadfence();
        const int prev = atomicAdd(&g_ticket, 1);
        s_last = (prev == NSEG - 1) ? 1 : 0;
    }
    __syncthreads();

    if (s_last && w == 0) {
        __threadfence();
        const float a  = g_partials[lane];
        const float b  = g_partials[lane + 32];
        const float c2 = g_partials[lane + 64];
        const float d2 = g_partials[lane + 96];
        float vsum = (a + b) + (c2 + d2);
        #pragma unroll
        for (int off = 16; off > 0; off >>= 1)
            vsum += __shfl_xor_sync(0xffffffffu, vsum, off);
        if (lane == 0) {
            out[0] = vsum * (1.0f / (float)(NSEG * P));
            g_ticket = 0;   // reset for next graph replay
        }
    }
}

extern "C" void kernel_launch(void* const* d_in, const int* in_sizes, int n_in,
                              void* d_out, int out_size)
{
    const float* center  = (const float*)d_in[0];  // (128, 64)    f32
    const float* outputs = (const float*)d_in[1];  // (128,512,64) f32
    const int*   labels  = (const int*)d_in[2];    // (128, 512)   i32

    lmnn_fused_kernel<<<NSEG, NT>>>(center, outputs, labels, (float*)d_out);
}

// round 9
// speedup vs baseline: 1.0462x; 1.0462x over previous
#include <cuda_runtime.h>
#include <math_constants.h>

#define NSEG 128
#define P    512
#define D    64
#define KT   15
#define NC   8
#define NT   1024
#define NW   (NT/32)

__device__ float g_partials[NSEG];
__device__ int   g_ticket = 0;   // reset by last block each launch

__global__ __launch_bounds__(NT, 1)
void lmnn_fused_kernel(const float* __restrict__ center,
                       const float* __restrict__ outputs,
                       const int*   __restrict__ labels,
                       float*       __restrict__ out)
{
    __shared__ int   slab[P];
    __shared__ short sidx[NC][16];
    __shared__ int   sCnt[NC];
    __shared__ float sS[NC];
    __shared__ float sM[NC];
    __shared__ float sred[NW];
    __shared__ int   s_last;

    const int seg  = blockIdx.x;
    const int t    = threadIdx.x;
    const int w    = t >> 5;
    const int lane = t & 31;
    const int col  = t & 15;

    const float4* __restrict__ out4 = (const float4*)(outputs + (size_t)seg * P * D);
    const float4* __restrict__ cen4 = (const float4*)(center + seg * D);

    // ---- Issue the 131KB main batch FIRST (coalesced, streaming) ----
    // 8192 float4s/segment; thread t takes g = t + 1024*s. col = d-offset.
    float4 v[8];
    #pragma unroll
    for (int s = 0; s < 8; ++s)
        v[s] = __ldcs(&out4[t + NT * s]);
    const float4 c4 = __ldg(&cen4[col]);

    // ---- Warps 0..7: class scan + per-class stats, under load flight ----
    // top_k over -dd has all finite entries equal (dist broadcast along k),
    // so jax tie-breaking selects the FIRST KT same-class indices.
    if (w < NC) {
        int lab[16];
        #pragma unroll
        for (int u = 0; u < 16; ++u)
            lab[u] = __ldg(&labels[seg * P + u * 32 + lane]);
        if (w == 0) {
            #pragma unroll
            for (int u = 0; u < 16; ++u)
                slab[u * 32 + lane] = lab[u];
        }
        int cnt = 0, taken = 0;                    // uniform across the warp
        #pragma unroll
        for (int u = 0; u < 16; ++u) {
            const bool m = (lab[u] == w);
            const unsigned mask = __ballot_sync(0xffffffffu, m);
            const int pc = __popc(mask);
            const int need = KT - taken;
            if (need > 0) {
                const int rank = __popc(mask & ((1u << lane) - 1u));
                if (m && rank < need)
                    sidx[w][taken + rank] = (short)(u * 32 + lane);
                taken += (pc < need) ? pc : need;
            }
            cnt += pc;
        }
        if (lane == 0) sCnt[w] = cnt;
        __syncwarp();

        // ---- preamble: distances of this class's first-KT targets ----
        // 2 lanes per target: lane pair (2j, 2j+1); half-row of 8 float4s each.
        const int j    = lane >> 1;
        const int half = lane & 1;
        float dj = 0.0f;
        if (j < KT && j < taken) {
            const int idx = sidx[w][j];
            const float4* row = out4 + idx * 16 + half * 8;
            float a = 0.0f;
            #pragma unroll
            for (int u = 0; u < 8; ++u) {
                const float4 x = __ldg(&row[u]);
                const float4 c = __ldg(&cen4[half * 8 + u]);
                const float dx = x.x - c.x, dy = x.y - c.y;
                const float dz = x.z - c.z, dw = x.w - c.w;
                a += dx * dx + dy * dy + dz * dz + dw * dw;
            }
            dj = a + __shfl_xor_sync(0xffffffffu, a, 1);
        } else {
            (void)__shfl_xor_sync(0xffffffffu, dj, 1);
        }
        // reduce sum/max over the KT targets (even lanes of valid pairs)
        const bool own = (half == 0) && (j < KT);
        float S  = own ? ((j < taken) ? dj : CUDART_INF_F) : 0.0f;
        float Mx = own ? ((j < taken) ? dj : CUDART_INF_F) : -CUDART_INF_F;
        #pragma unroll
        for (int off = 16; off > 0; off >>= 1) {
            S += __shfl_xor_sync(0xffffffffu, S, off);
            Mx = fmaxf(Mx, __shfl_xor_sync(0xffffffffu, Mx, off));
        }
        if (lane == 0) {
            sS[w] = (cnt > 0) ? S : 0.0f;
            sM[w] = (cnt > 0) ? Mx : -CUDART_INF_F;
        }
    }
    __syncthreads();   // stats + slab ready

    // ---- margin_seg = 1 + max over present classes ----
    float ms = -CUDART_INF_F;
    #pragma unroll
    for (int c = 0; c < NC; ++c)
        ms = fmaxf(ms, sM[c]);
    ms += 1.0f;

    // ---- main loop: distance + INLINE push term; no sdist staging ----
    float acc = 0.0f;
    #pragma unroll
    for (int s = 0; s < 8; ++s) {
        const int g = t + NT * s;
        const float dx = v[s].x - c4.x;
        const float dy = v[s].y - c4.y;
        const float dz = v[s].z - c4.z;
        const float dw = v[s].w - c4.w;
        float part = dx * dx + dy * dy + dz * dz + dw * dw;
        part += __shfl_down_sync(0xffffffffu, part, 8);
        part += __shfl_down_sync(0xffffffffu, part, 4);
        part += __shfl_down_sync(0xffffffffu, part, 2);
        part += __shfl_down_sync(0xffffffffu, part, 1);
        if (col == 0) {
            const int   pt = g >> 4;
            const int   cj = slab[pt];
            if (part < ms)
                acc += (float)(P - sCnt[cj]) * fmaxf(1.0f + sM[cj] - part, 0.0f);
        }
    }

    // ---- block reduce: acc lives at lanes 0 and 16 of each warp ----
    acc += __shfl_down_sync(0xffffffffu, acc, 16);
    if (lane == 0) sred[w] = acc;
    __syncthreads();

    if (t == 0) {
        float push = 0.0f;
        #pragma unroll
        for (int k = 0; k < NW; ++k) push += sred[k];
        float pull = 0.0f;
        #pragma unroll
        for (int c = 0; c < NC; ++c)
            pull += (float)sCnt[c] * sS[c];
        g_partials[seg] = pull + push;
        __threadfence();
        const int prev = atomicAdd(&g_ticket, 1);
        s_last = (prev == NSEG - 1) ? 1 : 0;
    }
    __syncthreads();

    if (s_last && w == 0) {
        __threadfence();
        const float a  = g_partials[lane];
        const float b  = g_partials[lane + 32];
        const float c2 = g_partials[lane + 64];
        const float d2 = g_partials[lane + 96];
        float vsum = (a + b) + (c2 + d2);
        #pragma unroll
        for (int off = 16; off > 0; off >>= 1)
            vsum += __shfl_xor_sync(0xffffffffu, vsum, off);
        if (lane == 0) {
            out[0] = vsum * (1.0f / (float)(NSEG * P));
            g_ticket = 0;   // reset for next graph replay
        }
    }
}

extern "C" void kernel_launch(void* const* d_in, const int* in_sizes, int n_in,
                              void* d_out, int out_size)
{
    const float* center  = (const float*)d_in[0];  // (128, 64)    f32
    const float* outputs = (const float*)d_in[1];  // (128,512,64) f32
    const int*   labels  = (const int*)d_in[2];    // (128, 512)   i32

    lmnn_fused_kernel<<<NSEG, NT>>>(center, outputs, labels, (float*)d_out);
}

// round 10
// speedup vs baseline: 1.2179x; 1.1642x over previous
#include <cuda_runtime.h>
#include <math_constants.h>

#define NSEG 128
#define P    512
#define D    64
#define KT   15
#define NC   8
#define NT   1024
#define NW   (NT/32)

__device__ float g_partials[NSEG];
__device__ int   g_ticket = 0;   // reset by last block each launch

// ---------- Kernel P: pure L2 prefetch, no consumers ----------
// One thread per 128B line of `outputs` (131072 lines total).
__global__ __launch_bounds__(NT, 1)
void lmnn_prefetch_kernel(const float* __restrict__ outputs)
{
    const char* p = (const char*)outputs +
                    ((size_t)blockIdx.x * NT + threadIdx.x) * 128;
    asm volatile("prefetch.global.L2 [%0];" :: "l"(p));
}

// ---------- Kernel M: fused LMNN loss (proven R5 skeleton) ----------
__global__ __launch_bounds__(NT, 1)
void lmnn_fused_kernel(const float* __restrict__ center,
                       const float* __restrict__ outputs,
                       const int*   __restrict__ labels,
                       float*       __restrict__ out)
{
    __shared__ float sdist[P];
    __shared__ int   slab[P];
    __shared__ short sidx[NC][16];
    __shared__ int   sCnt[NC];
    __shared__ int   sTaken[NC];
    __shared__ float sS[NC];
    __shared__ float sM[NC];
    __shared__ float sred[NW];
    __shared__ int   s_last;

    const int seg  = blockIdx.x;
    const int t    = threadIdx.x;
    const int w    = t >> 5;
    const int lane = t & 31;
    const int col  = t & 15;

    // ---- front-batched coalesced loads (default policy: want L2 hits) ----
    // 8192 float4s/segment; thread t takes g = t + 1024*s. col = d-offset.
    const float4* __restrict__ out4 = (const float4*)(outputs + (size_t)seg * P * D);
    float4 v[8];
    #pragma unroll
    for (int s = 0; s < 8; ++s)
        v[s] = out4[t + NT * s];
    const float4 c4 = __ldg(&((const float4*)(center + seg * D))[col]);

    // ---- class scan on labels (warps 0..7), hidden under load flight ----
    // top_k over -dd has all finite entries equal (dist broadcast along k),
    // so jax tie-breaking selects the FIRST KT same-class indices.
    if (w < NC) {
        int lab[16];
        #pragma unroll
        for (int u = 0; u < 16; ++u)
            lab[u] = __ldg(&labels[seg * P + u * 32 + lane]);
        if (w == 0) {
            #pragma unroll
            for (int u = 0; u < 16; ++u)
                slab[u * 32 + lane] = lab[u];
        }
        int cnt = 0, taken = 0;
        #pragma unroll
        for (int u = 0; u < 16; ++u) {
            const bool m = (lab[u] == w);
            const unsigned mask = __ballot_sync(0xffffffffu, m);
            const int pc = __popc(mask);
            const int need = KT - taken;
            if (need > 0) {
                const int rank = __popc(mask & ((1u << lane) - 1u));
                if (m && rank < need)
                    sidx[w][taken + rank] = (short)(u * 32 + lane);
                taken += (pc < need) ? pc : need;
            }
            cnt += pc;
        }
        if (lane == 0) { sCnt[w] = cnt; sTaken[w] = taken; }
    }

    // ---- distance compute: 16 lanes = one point ----
    #pragma unroll
    for (int s = 0; s < 8; ++s) {
        const int g = t + NT * s;
        const float dx = v[s].x - c4.x;
        const float dy = v[s].y - c4.y;
        const float dz = v[s].z - c4.z;
        const float dw = v[s].w - c4.w;
        float part = dx * dx + dy * dy + dz * dz + dw * dw;
        part += __shfl_down_sync(0xffffffffu, part, 8);
        part += __shfl_down_sync(0xffffffffu, part, 4);
        part += __shfl_down_sync(0xffffffffu, part, 2);
        part += __shfl_down_sync(0xffffffffu, part, 1);
        if (col == 0) sdist[g >> 4] = part;
    }
    __syncthreads();

    // ---- gather first-KT distances per class (warps 0..7) ----
    if (w < NC) {
        const int cnt   = sCnt[w];
        const int taken = sTaken[w];
        float d = (lane < KT)
                    ? ((lane < taken) ? sdist[sidx[w][lane]] : CUDART_INF_F)
                    : 0.0f;
        float S  = (lane < KT) ? d : 0.0f;
        float Mx = (lane < KT) ? d : -CUDART_INF_F;
        #pragma unroll
        for (int off = 16; off > 0; off >>= 1) {
            S += __shfl_xor_sync(0xffffffffu, S, off);
            Mx = fmaxf(Mx, __shfl_xor_sync(0xffffffffu, Mx, off));
        }
        if (lane == 0) {
            sS[w] = (cnt > 0) ? S : 0.0f;
            sM[w] = (cnt > 0) ? Mx : -CUDART_INF_F;
        }
    }
    __syncthreads();

    // ---- margin_seg = 1 + max over present classes ----
    float ms = -CUDART_INF_F;
    #pragma unroll
    for (int c = 0; c < NC; ++c)
        ms = fmaxf(ms, sM[c]);
    ms += 1.0f;

    // ---- push term per point (first 512 threads) ----
    float term = 0.0f;
    if (t < P) {
        const int   cj = slab[t];
        const float dv = sdist[t];
        if (dv < ms)
            term = (float)(P - sCnt[cj]) * fmaxf(1.0f + sM[cj] - dv, 0.0f);
    }
    #pragma unroll
    for (int off = 16; off > 0; off >>= 1)
        term += __shfl_xor_sync(0xffffffffu, term, off);
    if (lane == 0) sred[w] = term;
    __syncthreads();

    // ---- per-segment partial + last-block finish ----
    if (t == 0) {
        float push = 0.0f;
        #pragma unroll
        for (int k = 0; k < NW; ++k) push += sred[k];
        float pull = 0.0f;
        #pragma unroll
        for (int c = 0; c < NC; ++c)
            pull += (float)sCnt[c] * sS[c];
        g_partials[seg] = pull + push;
        __threadfence();
        const int prev = atomicAdd(&g_ticket, 1);
        s_last = (prev == NSEG - 1) ? 1 : 0;
    }
    __syncthreads();

    if (s_last && w == 0) {
        __threadfence();
        const float a  = g_partials[lane];
        const float b  = g_partials[lane + 32];
        const float c2 = g_partials[lane + 64];
        const float d2 = g_partials[lane + 96];
        float vsum = (a + b) + (c2 + d2);
        #pragma unroll
        for (int off = 16; off > 0; off >>= 1)
            vsum += __shfl_xor_sync(0xffffffffu, vsum, off);
        if (lane == 0) {
            out[0] = vsum * (1.0f / (float)(NSEG * P));
            g_ticket = 0;   // reset for next graph replay
        }
    }
}

extern "C" void kernel_launch(void* const* d_in, const int* in_sizes, int n_in,
                              void* d_out, int out_size)
{
    const float* center  = (const float*)d_in[0];  // (128, 64)    f32
    const float* outputs = (const float*)d_in[1];  // (128,512,64) f32
    const int*   labels  = (const int*)d_in[2];    // (128, 512)   i32

    lmnn_prefetch_kernel<<<NSEG, NT>>>(outputs);
    lmnn_fused_kernel<<<NSEG, NT>>>(center, outputs, labels, (float*)d_out);
}